// round 15
// baseline (speedup 1.0000x reference)
#include <cuda_runtime.h>
#include <cuda_fp16.h>
#include <cstdint>
#include <math.h>

#define N_TOK 1024
#define HID   2048
#define NEXP  8
#define IMOE  1408
#define ISH   5632
#define QI    (ISH / 4)     // 1408, gu0 n-quarter / dn1 k-chunk

// ---------------- scratch (device globals; no allocation allowed) ----------------
__device__ float g_part [(size_t)N_TOK * 2 * HID];
__device__ float g_sg  [N_TOK];
__device__ float g_wt  [NEXP * N_TOK];
__device__ int   g_cnt [NEXP];
__device__ int   g_tok [NEXP * N_TOK];
__device__ int   g_slot[NEXP * N_TOK];

// fp16 operand mirrors
__device__ __half h_x    [(size_t)N_TOK * HID];
__device__ __half h_swgu [(size_t)HID * (2 * ISH)];
__device__ __half h_swd  [(size_t)ISH * HID];
__device__ __half h_wgu  [(size_t)NEXP * HID * (2 * IMOE)];
__device__ __half h_wd   [(size_t)NEXP * IMOE * HID];
__device__ __half h_act_s[(size_t)N_TOK * ISH];
__device__ __half h_act_e[(size_t)NEXP * N_TOK * IMOE];

// ---------------- helpers ----------------
__device__ __forceinline__ float siluf(float v) { return v / (1.f + expf(-v)); }

__device__ __forceinline__ void mma_f16(float* c, const unsigned* a, const unsigned* b) {
    asm volatile(
        "mma.sync.aligned.m16n8k16.row.col.f32.f16.f16.f32 "
        "{%0,%1,%2,%3}, {%4,%5,%6,%7}, {%8,%9}, {%0,%1,%2,%3};\n"
        : "+f"(c[0]), "+f"(c[1]), "+f"(c[2]), "+f"(c[3])
        : "r"(a[0]), "r"(a[1]), "r"(a[2]), "r"(a[3]), "r"(b[0]), "r"(b[1]));
}
__device__ __forceinline__ void ldsm_x4(unsigned* r, uint32_t a) {
    asm volatile("ldmatrix.sync.aligned.m8n8.x4.shared.b16 {%0,%1,%2,%3}, [%4];"
        : "=r"(r[0]), "=r"(r[1]), "=r"(r[2]), "=r"(r[3]) : "r"(a));
}
__device__ __forceinline__ void ldsm_x4_t(unsigned* r, uint32_t a) {
    asm volatile("ldmatrix.sync.aligned.m8n8.x4.trans.shared.b16 {%0,%1,%2,%3}, [%4];"
        : "=r"(r[0]), "=r"(r[1]), "=r"(r[2]), "=r"(r[3]) : "r"(a));
}
__device__ __forceinline__ void cp16(uint32_t dst, const void* src) {
    asm volatile("cp.async.cg.shared.global [%0], [%1], 16;\n" :: "r"(dst), "l"(src));
}
__device__ __forceinline__ void cp_commit() { asm volatile("cp.async.commit_group;\n"); }
template<int W> __device__ __forceinline__ void cp_wait() {
    asm volatile("cp.async.wait_group %0;\n" :: "n"(W));
}
__device__ __forceinline__ uint4 pack8(float4 v0, float4 v1) {
    __half2 a = __floats2half2_rn(v0.x, v0.y);
    __half2 b = __floats2half2_rn(v0.z, v0.w);
    __half2 c = __floats2half2_rn(v1.x, v1.y);
    __half2 d = __floats2half2_rn(v1.z, v1.w);
    return make_uint4(*(unsigned*)&a, *(unsigned*)&b, *(unsigned*)&c, *(unsigned*)&d);
}

// ---------------- fp32 -> fp16 flat convert ----------------
// W: 2=swd, 3=wgu, 4=wd
template<int W>
__global__ void f2h_kernel(const float4* __restrict__ src, int n8) {
    int i = blockIdx.x * blockDim.x + threadIdx.x;
    if (i >= n8) return;
    __half* dst;
    if      (W == 2) dst = h_swd;
    else if (W == 3) dst = h_wgu;
    else             dst = h_wd;
    uint4 u = pack8(src[2 * i], src[2 * i + 1]);
    *(uint4*)(dst + (size_t)i * 8) = u;
}

// ---------------- swgu column-strip convert ----------------
__global__ void f2h_swgu_strip(const float* __restrict__ src, int cb) {
    const int perrow = QI / 8;                 // 176
    const int total = HID * perrow * 2;
    int idx = blockIdx.x * blockDim.x + threadIdx.x;
    if (idx >= total) return;
    int half = idx / (HID * perrow);
    int rem  = idx % (HID * perrow);
    int r = rem / perrow;
    int col = cb + half * ISH + (rem % perrow) * 8;
    const float4* s = (const float4*)(src + (size_t)r * (2 * ISH) + col);
    uint4 u = pack8(s[0], s[1]);
    *(uint4*)(h_swgu + (size_t)r * (2 * ISH) + col) = u;
}

// ---------------- init ----------------
__global__ void init_kernel() {
    if (threadIdx.x < NEXP) g_cnt[threadIdx.x] = 0;
}

// ---------------- router (also emits h_x) ----------------
__global__ void router_kernel(const float* __restrict__ x,
                              const float* __restrict__ gate_w,
                              const float* __restrict__ sgate_w) {
    int n = blockIdx.x;
    int w = threadIdx.x >> 5, lane = threadIdx.x & 31;
    const float* xr = x + (size_t)n * HID;
    __shared__ float s_log[NEXP];
    __shared__ float s_sg;

    float acc = 0.f, accs = 0.f;
    for (int h = lane; h < HID; h += 32) {
        float xv = xr[h];
        acc += xv * gate_w[h * NEXP + w];
        if (w == 0) { accs += xv * sgate_w[h]; h_x[(size_t)n * HID + h] = __float2half(xv); }
    }
    #pragma unroll
    for (int o = 16; o > 0; o >>= 1) {
        acc  += __shfl_down_sync(0xffffffffu, acc, o);
        accs += __shfl_down_sync(0xffffffffu, accs, o);
    }
    if (lane == 0) { s_log[w] = acc; if (w == 0) s_sg = accs; }
    __syncthreads();

    if (threadIdx.x == 0) {
        float mx = s_log[0];
        #pragma unroll
        for (int e = 1; e < NEXP; e++) mx = fmaxf(mx, s_log[e]);
        float p[NEXP], den = 0.f;
        #pragma unroll
        for (int e = 0; e < NEXP; e++) { p[e] = expf(s_log[e] - mx); den += p[e]; }
        float inv = 1.f / den;
        #pragma unroll
        for (int e = 0; e < NEXP; e++) p[e] *= inv;
        int e0 = 0;
        #pragma unroll
        for (int e = 1; e < NEXP; e++) if (p[e] > p[e0]) e0 = e;
        int e1 = (e0 == 0) ? 1 : 0;
        #pragma unroll
        for (int e = 0; e < NEXP; e++) if (e != e0 && p[e] > p[e1]) e1 = e;
        int es[2] = {e0, e1};
        #pragma unroll
        for (int k = 0; k < 2; k++) {
            int e = es[k];
            int pos = atomicAdd(&g_cnt[e], 1);
            g_tok [e * N_TOK + pos] = n;
            g_slot[e * N_TOK + pos] = k;
            g_wt  [e * N_TOK + pos] = p[e];
        }
        g_sg[n] = 1.f / (1.f + expf(-s_sg));
    }
}

// =======================================================================================
#define BM 128
#define BN 128
#define BK 32
#define A_PITCH 40
#define B_PITCH 136
#define A64_BYTES (64 * A_PITCH * 2)   // 5120  (BM=64 expert kernels, BK=32)
#define B_BYTES (BK * B_PITCH * 2)     // 8704

// ---- BK=64 shared-chain constants ----
#define BK2 64
#define A2_PITCH 72                        // 64 halves + 8 pad (9x16B, conflict-free)
#define A2_BYTES (BM * A2_PITCH * 2)       // 18432
#define B2_BYTES (BK2 * B_PITCH * 2)       // 17408

// ---------------- FUSED gate_up GEMM + SiLU*up (shared expert, BM=128, BK=64) ----------------
#define FSTAGES 3
#define F64STG_B (A64_BYTES + 2 * B_BYTES)   // 22528 (expert gu, BK=32)
#define G0STG_B  (A2_BYTES + 2 * B2_BYTES)   // 53248 (shared gu, BK=64)

__global__ void __launch_bounds__(256)
gemm_gu0(int K, int Nb, int Iact, int n_base) {
    extern __shared__ __half smem[];

    const int tid  = threadIdx.x;
    const int lane = tid & 31, warp = tid >> 5;
    const int wm = warp & 1, wn = warp >> 1;

    const int m0 = blockIdx.y * BM;
    const int n0 = n_base + blockIdx.x * BN;

    const __half* B = h_swgu;

    // A loader: row = tid>>1, 32-half span (4 cp16) at (tid&1)*32
    const int ar = tid >> 1;               // 0..127
    const int ac = (tid & 1) * 32;         // halves
    const __half* aP = h_x + (size_t)(m0 + ar) * HID;
    // B loader: k-rows bk+16r (r=0..3), chunk bc
    const int bk = tid >> 4, bc = (tid & 15) * 8;
    const __half* bPg = B + n0;
    const __half* bPu = B + Iact + n0;

    const uint32_t sbase = (uint32_t)__cvta_generic_to_shared(smem);
    const uint32_t dA = sbase + (uint32_t)(ar * A2_PITCH + ac) * 2u;
    const uint32_t dG = sbase + (uint32_t)A2_BYTES + (uint32_t)(bk * B_PITCH + bc) * 2u;
    const uint32_t dU = dG + (uint32_t)B2_BYTES;

    const int ktiles = K / BK2;            // 32

    float accg[4][4][4], accu[4][4][4];
    #pragma unroll
    for (int i = 0; i < 4; i++)
        #pragma unroll
        for (int j = 0; j < 4; j++)
            #pragma unroll
            for (int q = 0; q < 4; q++) { accg[i][j][q] = 0.f; accu[i][j][q] = 0.f; }

    #pragma unroll
    for (int s = 0; s < FSTAGES - 1; s++) {
        const int k0 = s * BK2;
        const uint32_t so = (uint32_t)(s * G0STG_B);
        #pragma unroll
        for (int c = 0; c < 4; c++)
            cp16(dA + so + (uint32_t)(c * 16), aP + k0 + ac + 8 * c);
        #pragma unroll
        for (int r = 0; r < 4; r++) {
            cp16(dG + so + (uint32_t)(16 * r * B_PITCH) * 2u, bPg + (size_t)(k0 + bk + 16 * r) * Nb + bc);
            cp16(dU + so + (uint32_t)(16 * r * B_PITCH) * 2u, bPu + (size_t)(k0 + bk + 16 * r) * Nb + bc);
        }
        cp_commit();
    }

    const int frow_l = (lane & 7) + ((lane >> 3) & 1) * 8;
    const int fhi_l  = (lane >> 4) & 1;
    const uint32_t aFrag = sbase + (uint32_t)(((wm * 64 + frow_l) * A2_PITCH) + fhi_l * 8) * 2u;
    const uint32_t gFrag = sbase + (uint32_t)A2_BYTES
                         + (uint32_t)((frow_l * B_PITCH) + wn * 32 + fhi_l * 8) * 2u;

    for (int kt = 0; kt < ktiles; kt++) {
        cp_wait<FSTAGES - 2>();
        __syncthreads();

        const int kn = kt + FSTAGES - 1;
        if (kn < ktiles) {
            const int k0 = kn * BK2;
            const uint32_t so = (uint32_t)((kn % FSTAGES) * G0STG_B);
            #pragma unroll
            for (int c = 0; c < 4; c++)
                cp16(dA + so + (uint32_t)(c * 16), aP + k0 + ac + 8 * c);
            #pragma unroll
            for (int r = 0; r < 4; r++) {
                cp16(dG + so + (uint32_t)(16 * r * B_PITCH) * 2u, bPg + (size_t)(k0 + bk + 16 * r) * Nb + bc);
                cp16(dU + so + (uint32_t)(16 * r * B_PITCH) * 2u, bPu + (size_t)(k0 + bk + 16 * r) * Nb + bc);
            }
        }
        cp_commit();

        const uint32_t so = (uint32_t)((kt % FSTAGES) * G0STG_B);
        #pragma unroll
        for (int ks = 0; ks < 4; ks++) {
            const int kk = ks * 16;
            unsigned af[4][4], bg[4][2], bu[4][2];
            #pragma unroll
            for (int i = 0; i < 4; i++)
                ldsm_x4(af[i], aFrag + so + (uint32_t)(i * 16 * A2_PITCH + kk) * 2u);
            #pragma unroll
            for (int p = 0; p < 2; p++) {
                unsigned t[4];
                ldsm_x4_t(t, gFrag + so + (uint32_t)(kk * B_PITCH + p * 16) * 2u);
                bg[2 * p][0] = t[0]; bg[2 * p][1] = t[1];
                bg[2 * p + 1][0] = t[2]; bg[2 * p + 1][1] = t[3];
                ldsm_x4_t(t, gFrag + so + (uint32_t)B2_BYTES + (uint32_t)(kk * B_PITCH + p * 16) * 2u);
                bu[2 * p][0] = t[0]; bu[2 * p][1] = t[1];
                bu[2 * p + 1][0] = t[2]; bu[2 * p + 1][1] = t[3];
            }
            #pragma unroll
            for (int i = 0; i < 4; i++)
                #pragma unroll
                for (int j = 0; j < 4; j++) {
                    mma_f16(accg[i][j], af[i], bg[j]);
                    mma_f16(accu[i][j], af[i], bu[j]);
                }
        }
    }

    const int g = lane >> 2, tg = lane & 3;
    #pragma unroll
    for (int i = 0; i < 4; i++) {
        #pragma unroll
        for (int half = 0; half < 2; half++) {
            int gr = m0 + wm * 64 + i * 16 + g + half * 8;
            __half* arow = h_act_s + (size_t)gr * Iact;
            #pragma unroll
            for (int j = 0; j < 4; j++) {
                int cc = n0 + wn * 32 + j * 8 + 2 * tg;
                float v0 = siluf(accg[i][j][half * 2 + 0]) * accu[i][j][half * 2 + 0];
                float v1 = siluf(accg[i][j][half * 2 + 1]) * accu[i][j][half * 2 + 1];
                __half2 hv = __floats2half2_rn(v0, v1);
                *(__half2*)(arow + cc) = hv;
            }
        }
    }
}

// ---------------- expert gate_up, BM=64, BK=32 (unchanged from round 14) ----------------
__global__ void __launch_bounds__(256)
gemm_gu64(int K, int Nb, int Iact) {
    extern __shared__ __half smem[];

    const int tid  = threadIdx.x;
    const int lane = tid & 31, warp = tid >> 5;
    const int wm = warp & 1, wn = warp >> 1;

    const int m0 = blockIdx.y * 64;
    const int n0 = blockIdx.x * BN;
    const int e  = blockIdx.z;

    const int Mrows = g_cnt[e];
    if (m0 >= Mrows) return;
    const __half* B = h_wgu + (size_t)e * HID * (2 * IMOE);

    const int ar = tid >> 2, ac = (tid & 3) * 8;
    const __half* aP0;
    {
        int r0 = m0 + ar;
        int i0 = (r0 < Mrows) ? g_tok[e * N_TOK + r0] : 0;
        aP0 = h_x + (size_t)i0 * HID;
    }
    const int bk = tid >> 4, bc = (tid & 15) * 8;
    const __half* bPg = B + n0;
    const __half* bPu = B + Iact + n0;

    const uint32_t sbase = (uint32_t)__cvta_generic_to_shared(smem);
    const uint32_t dA0 = sbase + (uint32_t)(ar * A_PITCH + ac) * 2u;
    const uint32_t dG0 = sbase + (uint32_t)A64_BYTES + (uint32_t)(bk * B_PITCH + bc) * 2u;
    const uint32_t dG1 = dG0 + 16u * B_PITCH * 2u;
    const uint32_t dU0 = dG0 + (uint32_t)B_BYTES;
    const uint32_t dU1 = dG1 + (uint32_t)B_BYTES;

    const int ktiles = K / BK;

    float accg[2][4][4], accu[2][4][4];
    #pragma unroll
    for (int i = 0; i < 2; i++)
        #pragma unroll
        for (int j = 0; j < 4; j++)
            #pragma unroll
            for (int q = 0; q < 4; q++) { accg[i][j][q] = 0.f; accu[i][j][q] = 0.f; }

    #pragma unroll
    for (int s = 0; s < FSTAGES - 1; s++) {
        const int k0 = s * BK;
        const uint32_t so = (uint32_t)(s * F64STG_B);
        cp16(dA0 + so, aP0 + k0 + ac);
        cp16(dG0 + so, bPg + (size_t)(k0 + bk) * Nb + bc);
        cp16(dG1 + so, bPg + (size_t)(k0 + bk + 16) * Nb + bc);
        cp16(dU0 + so, bPu + (size_t)(k0 + bk) * Nb + bc);
        cp16(dU1 + so, bPu + (size_t)(k0 + bk + 16) * Nb + bc);
        cp_commit();
    }

    const int frow_l = (lane & 7) + ((lane >> 3) & 1) * 8;
    const int fhi_l  = (lane >> 4) & 1;
    const uint32_t aFrag = sbase + (uint32_t)(((wm * 32 + frow_l) * A_PITCH) + fhi_l * 8) * 2u;
    const uint32_t gFrag = sbase + (uint32_t)A64_BYTES
                         + (uint32_t)((frow_l * B_PITCH) + wn * 32 + fhi_l * 8) * 2u;

    for (int kt = 0; kt < ktiles; kt++) {
        cp_wait<FSTAGES - 2>();
        __syncthreads();

        const int kn = kt + FSTAGES - 1;
        if (kn < ktiles) {
            const int k0 = kn * BK;
            const uint32_t so = (uint32_t)((kn % FSTAGES) * F64STG_B);
            cp16(dA0 + so, aP0 + k0 + ac);
            cp16(dG0 + so, bPg + (size_t)(k0 + bk) * Nb + bc);
            cp16(dG1 + so, bPg + (size_t)(k0 + bk + 16) * Nb + bc);
            cp16(dU0 + so, bPu + (size_t)(k0 + bk) * Nb + bc);
            cp16(dU1 + so, bPu + (size_t)(k0 + bk + 16) * Nb + bc);
        }
        cp_commit();

        const uint32_t so = (uint32_t)((kt % FSTAGES) * F64STG_B);
        #pragma unroll
        for (int ks = 0; ks < 2; ks++) {
            const int kk = ks * 16;
            unsigned af[2][4], bg[4][2], bu[4][2];
            #pragma unroll
            for (int i = 0; i < 2; i++)
                ldsm_x4(af[i], aFrag + so + (uint32_t)(i * 16 * A_PITCH + kk) * 2u);
            #pragma unroll
            for (int p = 0; p < 2; p++) {
                unsigned t[4];
                ldsm_x4_t(t, gFrag + so + (uint32_t)(kk * B_PITCH + p * 16) * 2u);
                bg[2 * p][0] = t[0]; bg[2 * p][1] = t[1];
                bg[2 * p + 1][0] = t[2]; bg[2 * p + 1][1] = t[3];
                ldsm_x4_t(t, gFrag + so + (uint32_t)B_BYTES + (uint32_t)(kk * B_PITCH + p * 16) * 2u);
                bu[2 * p][0] = t[0]; bu[2 * p][1] = t[1];
                bu[2 * p + 1][0] = t[2]; bu[2 * p + 1][1] = t[3];
            }
            #pragma unroll
            for (int i = 0; i < 2; i++)
                #pragma unroll
                for (int j = 0; j < 4; j++) {
                    mma_f16(accg[i][j], af[i], bg[j]);
                    mma_f16(accu[i][j], af[i], bu[j]);
                }
        }
    }

    const int g = lane >> 2, tg = lane & 3;
    #pragma unroll
    for (int i = 0; i < 2; i++) {
        #pragma unroll
        for (int half = 0; half < 2; half++) {
            int gr = m0 + wm * 32 + i * 16 + g + half * 8;
            if (gr >= Mrows) continue;
            float w = g_wt[e * N_TOK + gr];
            __half* arow = h_act_e + ((size_t)e * N_TOK + gr) * Iact;
            #pragma unroll
            for (int j = 0; j < 4; j++) {
                int cc = n0 + wn * 32 + j * 8 + 2 * tg;
                float v0 = w * siluf(accg[i][j][half * 2 + 0]) * accu[i][j][half * 2 + 0];
                float v1 = w * siluf(accg[i][j][half * 2 + 1]) * accu[i][j][half * 2 + 1];
                __half2 hv = __floats2half2_rn(v0, v1);
                *(__half2*)(arow + cc) = hv;
            }
        }
    }
}

// ---------------- shared down-proj (BM=128, BK=64, k-sliced accumulate) ----------------
#define STAGES 4
#define D64STG_B (A64_BYTES + B_BYTES)   // 13824 (expert dn, BK=32)
#define DN1STG_B (A2_BYTES + B2_BYTES)   // 35840 (shared dn, BK=64)

__global__ void __launch_bounds__(256)
gemm_dn1(float* __restrict__ Cg, int Kstride, int N, int kbeg, int klen, int accum) {
    extern __shared__ __half smem[];

    const int tid  = threadIdx.x;
    const int lane = tid & 31, warp = tid >> 5;
    const int wm = warp & 1, wn = warp >> 1;

    const int m0 = blockIdx.y * BM;
    const int n0 = blockIdx.x * BN;

    const __half* A = h_act_s;
    const __half* B = h_swd;

    const int ar = tid >> 1;
    const int ac = (tid & 1) * 32;
    const __half* aP = A + (size_t)(m0 + ar) * Kstride + kbeg;
    const int bk = tid >> 4, bc = (tid & 15) * 8;
    const __half* bP = B + (size_t)kbeg * N + n0;

    const uint32_t sbase = (uint32_t)__cvta_generic_to_shared(smem);
    const uint32_t dA = sbase + (uint32_t)(ar * A2_PITCH + ac) * 2u;
    const uint32_t dB = sbase + (uint32_t)A2_BYTES + (uint32_t)(bk * B_PITCH + bc) * 2u;

    const int ktiles = klen / BK2;     // 22

    float acc[4][4][4];
    #pragma unroll
    for (int i = 0; i < 4; i++)
        #pragma unroll
        for (int j = 0; j < 4; j++)
            #pragma unroll
            for (int q = 0; q < 4; q++) acc[i][j][q] = 0.f;

    #pragma unroll
    for (int s = 0; s < STAGES - 1; s++) {
        const int k0 = s * BK2;
        const uint32_t so = (uint32_t)(s * DN1STG_B);
        #pragma unroll
        for (int c = 0; c < 4; c++)
            cp16(dA + so + (uint32_t)(c * 16), aP + k0 + ac + 8 * c);
        #pragma unroll
        for (int r = 0; r < 4; r++)
            cp16(dB + so + (uint32_t)(16 * r * B_PITCH) * 2u, bP + (size_t)(k0 + bk + 16 * r) * N + bc);
        cp_commit();
    }

    const int frow_l = (lane & 7) + ((lane >> 3) & 1) * 8;
    const int fhi_l  = (lane >> 4) & 1;
    const uint32_t aFrag = sbase + (uint32_t)(((wm * 64 + frow_l) * A2_PITCH) + fhi_l * 8) * 2u;
    const uint32_t bFrag = sbase + (uint32_t)A2_BYTES
                         + (uint32_t)((frow_l * B_PITCH) + wn * 32 + fhi_l * 8) * 2u;

    for (int kt = 0; kt < ktiles; kt++) {
        cp_wait<STAGES - 2>();
        __syncthreads();

        const int kn = kt + STAGES - 1;
        if (kn < ktiles) {
            const int k0 = kn * BK2;
            const uint32_t so = (uint32_t)((kn & (STAGES - 1)) * DN1STG_B);
            #pragma unroll
            for (int c = 0; c < 4; c++)
                cp16(dA + so + (uint32_t)(c * 16), aP + k0 + ac + 8 * c);
            #pragma unroll
            for (int r = 0; r < 4; r++)
                cp16(dB + so + (uint32_t)(16 * r * B_PITCH) * 2u, bP + (size_t)(k0 + bk + 16 * r) * N + bc);
        }
        cp_commit();

        const uint32_t so = (uint32_t)((kt & (STAGES - 1)) * DN1STG_B);
        #pragma unroll
        for (int ks = 0; ks < 4; ks++) {
            const int kk = ks * 16;
            unsigned af[4][4], bf[4][2];
            #pragma unroll
            for (int i = 0; i < 4; i++)
                ldsm_x4(af[i], aFrag + so + (uint32_t)(i * 16 * A2_PITCH + kk) * 2u);
            #pragma unroll
            for (int p = 0; p < 2; p++) {
                unsigned t[4];
                ldsm_x4_t(t, bFrag + so + (uint32_t)(kk * B_PITCH + p * 16) * 2u);
                bf[2 * p][0] = t[0]; bf[2 * p][1] = t[1];
                bf[2 * p + 1][0] = t[2]; bf[2 * p + 1][1] = t[3];
            }
            #pragma unroll
            for (int i = 0; i < 4; i++)
                #pragma unroll
                for (int j = 0; j < 4; j++)
                    mma_f16(acc[i][j], af[i], bf[j]);
        }
    }

    const int g = lane >> 2, tg = lane & 3;
    #pragma unroll
    for (int i = 0; i < 4; i++) {
        #pragma unroll
        for (int half = 0; half < 2; half++) {
            int gr = m0 + wm * 64 + i * 16 + g + half * 8;
            float* crow = Cg + (size_t)gr * (size_t)N;
            float scale = g_sg[gr];
            #pragma unroll
            for (int j = 0; j < 4; j++) {
                int cc = n0 + wn * 32 + j * 8 + 2 * tg;
                float2 v = make_float2(acc[i][j][half * 2 + 0] * scale,
                                       acc[i][j][half * 2 + 1] * scale);
                if (accum) {
                    float2 o = *(float2*)(crow + cc);
                    v.x += o.x; v.y += o.y;
                }
                *(float2*)(crow + cc) = v;
            }
        }
    }
}

// ---------------- expert down-proj, BM=64, BK=32 (unchanged from round 14) ----------------
__global__ void __launch_bounds__(256)
gemm_dn64(int Kstride, int N) {
    extern __shared__ __half smem[];

    const int tid  = threadIdx.x;
    const int lane = tid & 31, warp = tid >> 5;
    const int wm = warp & 1, wn = warp >> 1;

    const int m0 = blockIdx.y * 64;
    const int n0 = blockIdx.x * BN;
    const int e  = blockIdx.z;

    const int Mrows = g_cnt[e];
    if (m0 >= Mrows) return;
    const __half* A = h_act_e + (size_t)e * N_TOK * IMOE;
    const __half* B = h_wd + (size_t)e * IMOE * HID;

    const int ar = tid >> 2, ac = (tid & 3) * 8;
    const __half* aP0;
    {
        int r0 = m0 + ar;
        if (r0 >= Mrows) r0 = m0;
        aP0 = A + (size_t)r0 * Kstride;
    }
    const int bk = tid >> 4, bc = (tid & 15) * 8;
    const __half* bP = B + n0;

    const uint32_t sbase = (uint32_t)__cvta_generic_to_shared(smem);
    const uint32_t dA0 = sbase + (uint32_t)(ar * A_PITCH + ac) * 2u;
    const uint32_t dB0 = sbase + (uint32_t)A64_BYTES + (uint32_t)(bk * B_PITCH + bc) * 2u;
    const uint32_t dB1 = dB0 + 16u * B_PITCH * 2u;

    const int ktiles = Kstride / BK;

    float acc[2][4][4];
    #pragma unroll
    for (int i = 0; i < 2; i++)
        #pragma unroll
        for (int j = 0; j < 4; j++)
            #pragma unroll
            for (int q = 0; q < 4; q++) acc[i][j][q] = 0.f;

    #pragma unroll
    for (int s = 0; s < STAGES - 1; s++) {
        const int k0 = s * BK;
        const uint32_t so = (uint32_t)(s * D64STG_B);
        cp16(dA0 + so, aP0 + k0 + ac);
        cp16(dB0 + so, bP + (size_t)(k0 + bk) * N + bc);
        cp16(dB1 + so, bP + (size_t)(k0 + bk + 16) * N + bc);
        cp_commit();
    }

    const int frow_l = (lane & 7) + ((lane >> 3) & 1) * 8;
    const int fhi_l  = (lane >> 4) & 1;
    const uint32_t aFrag = sbase + (uint32_t)(((wm * 32 + frow_l) * A_PITCH) + fhi_l * 8) * 2u;
    const uint32_t bFrag = sbase + (uint32_t)A64_BYTES
                         + (uint32_t)((frow_l * B_PITCH) + wn * 32 + fhi_l * 8) * 2u;

    for (int kt = 0; kt < ktiles; kt++) {
        cp_wait<STAGES - 2>();
        __syncthreads();

        const int kn = kt + STAGES - 1;
        if (kn < ktiles) {
            const int k0 = kn * BK;
            const uint32_t so = (uint32_t)((kn & (STAGES - 1)) * D64STG_B);
            cp16(dA0 + so, aP0 + k0 + ac);
            cp16(dB0 + so, bP + (size_t)(k0 + bk) * N + bc);
            cp16(dB1 + so, bP + (size_t)(k0 + bk + 16) * N + bc);
        }
        cp_commit();

        const uint32_t so = (uint32_t)((kt & (STAGES - 1)) * D64STG_B);
        #pragma unroll
        for (int ks = 0; ks < 2; ks++) {
            const int kk = ks * 16;
            unsigned af[2][4], bf[4][2];
            #pragma unroll
            for (int i = 0; i < 2; i++)
                ldsm_x4(af[i], aFrag + so + (uint32_t)(i * 16 * A_PITCH + kk) * 2u);
            #pragma unroll
            for (int p = 0; p < 2; p++) {
                unsigned t[4];
                ldsm_x4_t(t, bFrag + so + (uint32_t)(kk * B_PITCH + p * 16) * 2u);
                bf[2 * p][0] = t[0]; bf[2 * p][1] = t[1];
                bf[2 * p + 1][0] = t[2]; bf[2 * p + 1][1] = t[3];
            }
            #pragma unroll
            for (int i = 0; i < 2; i++)
                #pragma unroll
                for (int j = 0; j < 4; j++)
                    mma_f16(acc[i][j], af[i], bf[j]);
        }
    }

    const int g = lane >> 2, tg = lane & 3;
    #pragma unroll
    for (int i = 0; i < 2; i++) {
        #pragma unroll
        for (int half = 0; half < 2; half++) {
            int gr = m0 + wm * 32 + i * 16 + g + half * 8;
            if (gr >= Mrows) continue;
            int t_ = g_tok [e * N_TOK + gr];
            int s_ = g_slot[e * N_TOK + gr];
            float* crow = g_part + ((size_t)t_ * 2 + s_) * (size_t)N;
            #pragma unroll
            for (int j = 0; j < 4; j++) {
                int cc = n0 + wn * 32 + j * 8 + 2 * tg;
                float2 v = make_float2(acc[i][j][half * 2 + 0],
                                       acc[i][j][half * 2 + 1]);
                *(float2*)(crow + cc) = v;
            }
        }
    }
}

// ---------------- combine ----------------
__global__ void combine_kernel(float* __restrict__ out) {
    int idx = blockIdx.x * blockDim.x + threadIdx.x;
    const int total = N_TOK * (HID / 4);
    if (idx >= total) return;
    int n  = idx / (HID / 4);
    int h4 = (idx % (HID / 4)) * 4;
    float4 o  = *(float4*)(out + (size_t)n * HID + h4);
    float4 p0 = *(const float4*)(g_part + ((size_t)n * 2 + 0) * HID + h4);
    float4 p1 = *(const float4*)(g_part + ((size_t)n * 2 + 1) * HID + h4);
    o.x += p0.x + p1.x; o.y += p0.y + p1.y;
    o.z += p0.z + p1.z; o.w += p0.w + p1.w;
    *(float4*)(out + (size_t)n * HID + h4) = o;
}

// ---------------- launch: round-14 schedule, BK=64 shared-chain kernels ----------------
extern "C" void kernel_launch(void* const* d_in, const int* in_sizes, int n_in,
                              void* d_out, int out_size) {
    const float* x    = (const float*)d_in[0];
    const float* gw   = (const float*)d_in[1];
    const float* wgu  = (const float*)d_in[2];
    const float* wd   = (const float*)d_in[3];
    const float* swgu = (const float*)d_in[4];
    const float* swd  = (const float*)d_in[5];
    const float* sgw  = (const float*)d_in[6];
    float* out = (float*)d_out;

    static cudaStream_t s1 = nullptr, s2 = nullptr, s3 = nullptr;
    static cudaEvent_t ev_fork, ev_rt, ev_st[4], ev_swd, ev_wd,
                       ev_g0[4], ev_dn1, ev_exp;
    if (s1 == nullptr) {
        cudaStreamCreateWithFlags(&s1, cudaStreamNonBlocking);
        cudaStreamCreateWithFlags(&s2, cudaStreamNonBlocking);
        cudaStreamCreateWithFlags(&s3, cudaStreamNonBlocking);
        cudaEventCreateWithFlags(&ev_fork, cudaEventDisableTiming);
        cudaEventCreateWithFlags(&ev_rt,   cudaEventDisableTiming);
        for (int q = 0; q < 4; q++) {
            cudaEventCreateWithFlags(&ev_st[q], cudaEventDisableTiming);
            cudaEventCreateWithFlags(&ev_g0[q], cudaEventDisableTiming);
        }
        cudaEventCreateWithFlags(&ev_swd,  cudaEventDisableTiming);
        cudaEventCreateWithFlags(&ev_wd,   cudaEventDisableTiming);
        cudaEventCreateWithFlags(&ev_dn1,  cudaEventDisableTiming);
        cudaEventCreateWithFlags(&ev_exp,  cudaEventDisableTiming);
    }

    const int g0smem  = FSTAGES * G0STG_B;   // 159744
    const int f64smem = FSTAGES * F64STG_B;  // 67584
    const int dn1smem = STAGES * DN1STG_B;   // 143360
    const int d64smem = STAGES * D64STG_B;   // 55296
    cudaFuncSetAttribute(gemm_gu0,  cudaFuncAttributeMaxDynamicSharedMemorySize, g0smem);
    cudaFuncSetAttribute(gemm_gu64, cudaFuncAttributeMaxDynamicSharedMemorySize, f64smem);
    cudaFuncSetAttribute(gemm_dn1,  cudaFuncAttributeMaxDynamicSharedMemorySize, dn1smem);
    cudaFuncSetAttribute(gemm_dn64, cudaFuncAttributeMaxDynamicSharedMemorySize, d64smem);

    // ---- fork ----
    init_kernel<<<1, 32>>>();
    cudaEventRecord(ev_fork, 0);
    cudaStreamWaitEvent(s1, ev_fork, 0);
    cudaStreamWaitEvent(s2, ev_fork, 0);
    cudaStreamWaitEvent(s3, ev_fork, 0);

    // s1: swgu strips first (unblock gu0 quarters asap), then swd, wd
    {
        const int sg = (HID * (QI / 8) * 2 + 255) / 256;
        for (int q = 0; q < 4; q++) {
            f2h_swgu_strip<<<sg, 256, 0, s1>>>(swgu, q * QI);
            cudaEventRecord(ev_st[q], s1);
        }
        int n8 = (ISH * HID) / 8;
        f2h_kernel<2><<<(n8 + 255) / 256, 256, 0, s1>>>((const float4*)swd, n8);
        cudaEventRecord(ev_swd, s1);
        n8 = (NEXP * IMOE * HID) / 8;
        f2h_kernel<4><<<(n8 + 255) / 256, 256, 0, s1>>>((const float4*)wd, n8);
        cudaEventRecord(ev_wd, s1);
    }

    // stream 0: router, then gu0 n-quarters gated on strip converts
    router_kernel<<<N_TOK, 256>>>(x, gw, sgw);
    cudaEventRecord(ev_rt, 0);
    for (int q = 0; q < 4; q++) {
        cudaStreamWaitEvent(0, ev_st[q], 0);
        gemm_gu0<<<dim3(QI / BN, N_TOK / BM, 1), 256, g0smem>>>(HID, 2 * ISH, ISH, q * QI);
        cudaEventRecord(ev_g0[q], 0);
    }

    // s3: dn1 k-chunks, chained quarter-by-quarter against gu0
    cudaStreamWaitEvent(s3, ev_swd, 0);
    for (int q = 0; q < 4; q++) {
        cudaStreamWaitEvent(s3, ev_g0[q], 0);
        gemm_dn1<<<dim3(HID / BN, N_TOK / BM, 1), 256, dn1smem, s3>>>(
            out, ISH, HID, q * QI, QI, q > 0 ? 1 : 0);
    }
    cudaEventRecord(ev_dn1, s3);

    // s2: wgu convert, then expert chain (BM=64 kernels)
    {
        int n8 = (NEXP * HID * 2 * IMOE) / 8;
        f2h_kernel<3><<<(n8 + 255) / 256, 256, 0, s2>>>((const float4*)wgu, n8);
    }
    cudaStreamWaitEvent(s2, ev_rt, 0);
    gemm_gu64<<<dim3(IMOE / BN, N_TOK / 64, NEXP), 256, f64smem, s2>>>(HID, 2 * IMOE, IMOE);
    cudaStreamWaitEvent(s2, ev_wd, 0);
    gemm_dn64<<<dim3(HID / BN, N_TOK / 64, NEXP), 256, d64smem, s2>>>(IMOE, HID);
    cudaEventRecord(ev_exp, s2);

    // join: combine on stream 0
    cudaStreamWaitEvent(0, ev_dn1, 0);
    cudaStreamWaitEvent(0, ev_exp, 0);
    {
        int total = N_TOK * (HID / 4);
        combine_kernel<<<(total + 255) / 256, 256>>>(out);
    }
}

// round 16
// speedup vs baseline: 1.0516x; 1.0516x over previous
#include <cuda_runtime.h>
#include <cuda_fp16.h>
#include <cstdint>
#include <math.h>

#define N_TOK 1024
#define HID   2048
#define NEXP  8
#define IMOE  1408
#define ISH   5632
#define QI    (ISH / 4)     // 1408, gu0 n-quarter / dn1 k-chunk

// ---------------- scratch (device globals; no allocation allowed) ----------------
__device__ float g_sg  [N_TOK];
__device__ float g_wt  [NEXP * N_TOK];
__device__ int   g_cnt [NEXP];
__device__ int   g_tok [NEXP * N_TOK];

// fp16 operand mirrors
__device__ __half h_x    [(size_t)N_TOK * HID];
__device__ __half h_swgu [(size_t)HID * (2 * ISH)];
__device__ __half h_swd  [(size_t)ISH * HID];
__device__ __half h_wgu  [(size_t)NEXP * HID * (2 * IMOE)];
__device__ __half h_wd   [(size_t)NEXP * IMOE * HID];
__device__ __half h_act_s[(size_t)N_TOK * ISH];
__device__ __half h_act_e[(size_t)NEXP * N_TOK * IMOE];

// ---------------- helpers ----------------
__device__ __forceinline__ float siluf(float v) { return v / (1.f + expf(-v)); }

__device__ __forceinline__ void mma_f16(float* c, const unsigned* a, const unsigned* b) {
    asm volatile(
        "mma.sync.aligned.m16n8k16.row.col.f32.f16.f16.f32 "
        "{%0,%1,%2,%3}, {%4,%5,%6,%7}, {%8,%9}, {%0,%1,%2,%3};\n"
        : "+f"(c[0]), "+f"(c[1]), "+f"(c[2]), "+f"(c[3])
        : "r"(a[0]), "r"(a[1]), "r"(a[2]), "r"(a[3]), "r"(b[0]), "r"(b[1]));
}
__device__ __forceinline__ void ldsm_x4(unsigned* r, uint32_t a) {
    asm volatile("ldmatrix.sync.aligned.m8n8.x4.shared.b16 {%0,%1,%2,%3}, [%4];"
        : "=r"(r[0]), "=r"(r[1]), "=r"(r[2]), "=r"(r[3]) : "r"(a));
}
__device__ __forceinline__ void ldsm_x4_t(unsigned* r, uint32_t a) {
    asm volatile("ldmatrix.sync.aligned.m8n8.x4.trans.shared.b16 {%0,%1,%2,%3}, [%4];"
        : "=r"(r[0]), "=r"(r[1]), "=r"(r[2]), "=r"(r[3]) : "r"(a));
}
__device__ __forceinline__ void cp16(uint32_t dst, const void* src) {
    asm volatile("cp.async.cg.shared.global [%0], [%1], 16;\n" :: "r"(dst), "l"(src));
}
__device__ __forceinline__ void cp_commit() { asm volatile("cp.async.commit_group;\n"); }
template<int W> __device__ __forceinline__ void cp_wait() {
    asm volatile("cp.async.wait_group %0;\n" :: "n"(W));
}
__device__ __forceinline__ uint4 pack8(float4 v0, float4 v1) {
    __half2 a = __floats2half2_rn(v0.x, v0.y);
    __half2 b = __floats2half2_rn(v0.z, v0.w);
    __half2 c = __floats2half2_rn(v1.x, v1.y);
    __half2 d = __floats2half2_rn(v1.z, v1.w);
    return make_uint4(*(unsigned*)&a, *(unsigned*)&b, *(unsigned*)&c, *(unsigned*)&d);
}

// ---------------- fp32 -> fp16 flat convert ----------------
// W: 2=swd, 3=wgu, 4=wd
template<int W>
__global__ void f2h_kernel(const float4* __restrict__ src, int n8) {
    int i = blockIdx.x * blockDim.x + threadIdx.x;
    if (i >= n8) return;
    __half* dst;
    if      (W == 2) dst = h_swd;
    else if (W == 3) dst = h_wgu;
    else             dst = h_wd;
    uint4 u = pack8(src[2 * i], src[2 * i + 1]);
    *(uint4*)(dst + (size_t)i * 8) = u;
}

// ---------------- swgu column-strip convert ----------------
__global__ void f2h_swgu_strip(const float* __restrict__ src, int cb) {
    const int perrow = QI / 8;                 // 176
    const int total = HID * perrow * 2;
    int idx = blockIdx.x * blockDim.x + threadIdx.x;
    if (idx >= total) return;
    int half = idx / (HID * perrow);
    int rem  = idx % (HID * perrow);
    int r = rem / perrow;
    int col = cb + half * ISH + (rem % perrow) * 8;
    const float4* s = (const float4*)(src + (size_t)r * (2 * ISH) + col);
    uint4 u = pack8(s[0], s[1]);
    *(uint4*)(h_swgu + (size_t)r * (2 * ISH) + col) = u;
}

// ---------------- init ----------------
__global__ void init_kernel() {
    if (threadIdx.x < NEXP) g_cnt[threadIdx.x] = 0;
}

// ---------------- router (also emits h_x) ----------------
__global__ void router_kernel(const float* __restrict__ x,
                              const float* __restrict__ gate_w,
                              const float* __restrict__ sgate_w) {
    int n = blockIdx.x;
    int w = threadIdx.x >> 5, lane = threadIdx.x & 31;
    const float* xr = x + (size_t)n * HID;
    __shared__ float s_log[NEXP];
    __shared__ float s_sg;

    float acc = 0.f, accs = 0.f;
    for (int h = lane; h < HID; h += 32) {
        float xv = xr[h];
        acc += xv * gate_w[h * NEXP + w];
        if (w == 0) { accs += xv * sgate_w[h]; h_x[(size_t)n * HID + h] = __float2half(xv); }
    }
    #pragma unroll
    for (int o = 16; o > 0; o >>= 1) {
        acc  += __shfl_down_sync(0xffffffffu, acc, o);
        accs += __shfl_down_sync(0xffffffffu, accs, o);
    }
    if (lane == 0) { s_log[w] = acc; if (w == 0) s_sg = accs; }
    __syncthreads();

    if (threadIdx.x == 0) {
        float mx = s_log[0];
        #pragma unroll
        for (int e = 1; e < NEXP; e++) mx = fmaxf(mx, s_log[e]);
        float p[NEXP], den = 0.f;
        #pragma unroll
        for (int e = 0; e < NEXP; e++) { p[e] = expf(s_log[e] - mx); den += p[e]; }
        float inv = 1.f / den;
        #pragma unroll
        for (int e = 0; e < NEXP; e++) p[e] *= inv;
        int e0 = 0;
        #pragma unroll
        for (int e = 1; e < NEXP; e++) if (p[e] > p[e0]) e0 = e;
        int e1 = (e0 == 0) ? 1 : 0;
        #pragma unroll
        for (int e = 0; e < NEXP; e++) if (e != e0 && p[e] > p[e1]) e1 = e;
        int es[2] = {e0, e1};
        #pragma unroll
        for (int k = 0; k < 2; k++) {
            int e = es[k];
            int pos = atomicAdd(&g_cnt[e], 1);
            g_tok[e * N_TOK + pos] = n;
            g_wt [e * N_TOK + pos] = p[e];
        }
        g_sg[n] = 1.f / (1.f + expf(-s_sg));
    }
}

// =======================================================================================
#define BM 128
#define BN 128
#define BK 32
#define A_PITCH 40
#define B_PITCH 136
#define A_BYTES (BM * A_PITCH * 2)     // 10240
#define A64_BYTES (64 * A_PITCH * 2)   // 5120
#define B_BYTES (BK * B_PITCH * 2)     // 8704

// ---------------- FUSED gate_up GEMM + SiLU*up (shared expert, BM=128) ----------------
#define FSTAGES 3
#define FSTG_B  (A_BYTES + 2 * B_BYTES)    // 27648
#define F64STG_B (A64_BYTES + 2 * B_BYTES) // 22528

__global__ void __launch_bounds__(256)
gemm_gu0(int K, int Nb, int Iact, int n_base) {
    extern __shared__ __half smem[];

    const int tid  = threadIdx.x;
    const int lane = tid & 31, warp = tid >> 5;
    const int wm = warp & 1, wn = warp >> 1;

    const int m0 = blockIdx.y * BM;
    const int n0 = n_base + blockIdx.x * BN;

    const __half* B = h_swgu;

    const int ar = tid >> 2, ac = (tid & 3) * 8;
    const __half* aP0 = h_x + (size_t)(m0 + ar) * HID;
    const __half* aP1 = h_x + (size_t)(m0 + ar + 64) * HID;
    const int bk = tid >> 4, bc = (tid & 15) * 8;
    const __half* bPg = B + n0;
    const __half* bPu = B + Iact + n0;

    const uint32_t sbase = (uint32_t)__cvta_generic_to_shared(smem);
    const uint32_t dA0 = sbase + (uint32_t)(ar * A_PITCH + ac) * 2u;
    const uint32_t dA1 = dA0 + 64u * A_PITCH * 2u;
    const uint32_t dG0 = sbase + (uint32_t)A_BYTES + (uint32_t)(bk * B_PITCH + bc) * 2u;
    const uint32_t dG1 = dG0 + 16u * B_PITCH * 2u;
    const uint32_t dU0 = dG0 + (uint32_t)B_BYTES;
    const uint32_t dU1 = dG1 + (uint32_t)B_BYTES;

    const int ktiles = K / BK;

    float accg[4][4][4], accu[4][4][4];
    #pragma unroll
    for (int i = 0; i < 4; i++)
        #pragma unroll
        for (int j = 0; j < 4; j++)
            #pragma unroll
            for (int q = 0; q < 4; q++) { accg[i][j][q] = 0.f; accu[i][j][q] = 0.f; }

    #pragma unroll
    for (int s = 0; s < FSTAGES - 1; s++) {
        const int k0 = s * BK;
        const uint32_t so = (uint32_t)(s * FSTG_B);
        cp16(dA0 + so, aP0 + k0 + ac);
        cp16(dA1 + so, aP1 + k0 + ac);
        cp16(dG0 + so, bPg + (size_t)(k0 + bk) * Nb + bc);
        cp16(dG1 + so, bPg + (size_t)(k0 + bk + 16) * Nb + bc);
        cp16(dU0 + so, bPu + (size_t)(k0 + bk) * Nb + bc);
        cp16(dU1 + so, bPu + (size_t)(k0 + bk + 16) * Nb + bc);
        cp_commit();
    }

    const int frow_l = (lane & 7) + ((lane >> 3) & 1) * 8;
    const int fhi_l  = (lane >> 4) & 1;
    const uint32_t aFrag = sbase + (uint32_t)(((wm * 64 + frow_l) * A_PITCH) + fhi_l * 8) * 2u;
    const uint32_t gFrag = sbase + (uint32_t)A_BYTES
                         + (uint32_t)((frow_l * B_PITCH) + wn * 32 + fhi_l * 8) * 2u;

    for (int kt = 0; kt < ktiles; kt++) {
        cp_wait<FSTAGES - 2>();
        __syncthreads();

        const int kn = kt + FSTAGES - 1;
        if (kn < ktiles) {
            const int k0 = kn * BK;
            const uint32_t so = (uint32_t)((kn % FSTAGES) * FSTG_B);
            cp16(dA0 + so, aP0 + k0 + ac);
            cp16(dA1 + so, aP1 + k0 + ac);
            cp16(dG0 + so, bPg + (size_t)(k0 + bk) * Nb + bc);
            cp16(dG1 + so, bPg + (size_t)(k0 + bk + 16) * Nb + bc);
            cp16(dU0 + so, bPu + (size_t)(k0 + bk) * Nb + bc);
            cp16(dU1 + so, bPu + (size_t)(k0 + bk + 16) * Nb + bc);
        }
        cp_commit();

        const uint32_t so = (uint32_t)((kt % FSTAGES) * FSTG_B);
        #pragma unroll
        for (int ks = 0; ks < 2; ks++) {
            const int kk = ks * 16;
            unsigned af[4][4], bg[4][2], bu[4][2];
            #pragma unroll
            for (int i = 0; i < 4; i++)
                ldsm_x4(af[i], aFrag + so + (uint32_t)(i * 16 * A_PITCH + kk) * 2u);
            #pragma unroll
            for (int p = 0; p < 2; p++) {
                unsigned t[4];
                ldsm_x4_t(t, gFrag + so + (uint32_t)(kk * B_PITCH + p * 16) * 2u);
                bg[2 * p][0] = t[0]; bg[2 * p][1] = t[1];
                bg[2 * p + 1][0] = t[2]; bg[2 * p + 1][1] = t[3];
                ldsm_x4_t(t, gFrag + so + (uint32_t)B_BYTES + (uint32_t)(kk * B_PITCH + p * 16) * 2u);
                bu[2 * p][0] = t[0]; bu[2 * p][1] = t[1];
                bu[2 * p + 1][0] = t[2]; bu[2 * p + 1][1] = t[3];
            }
            #pragma unroll
            for (int i = 0; i < 4; i++)
                #pragma unroll
                for (int j = 0; j < 4; j++) {
                    mma_f16(accg[i][j], af[i], bg[j]);
                    mma_f16(accu[i][j], af[i], bu[j]);
                }
        }
    }

    const int g = lane >> 2, tg = lane & 3;
    #pragma unroll
    for (int i = 0; i < 4; i++) {
        #pragma unroll
        for (int half = 0; half < 2; half++) {
            int gr = m0 + wm * 64 + i * 16 + g + half * 8;
            __half* arow = h_act_s + (size_t)gr * Iact;
            #pragma unroll
            for (int j = 0; j < 4; j++) {
                int cc = n0 + wn * 32 + j * 8 + 2 * tg;
                float v0 = siluf(accg[i][j][half * 2 + 0]) * accu[i][j][half * 2 + 0];
                float v1 = siluf(accg[i][j][half * 2 + 1]) * accu[i][j][half * 2 + 1];
                __half2 hv = __floats2half2_rn(v0, v1);
                *(__half2*)(arow + cc) = hv;
            }
        }
    }
}

// ---------------- expert gate_up, BM=64 ----------------
__global__ void __launch_bounds__(256)
gemm_gu64(int K, int Nb, int Iact) {
    extern __shared__ __half smem[];

    const int tid  = threadIdx.x;
    const int lane = tid & 31, warp = tid >> 5;
    const int wm = warp & 1, wn = warp >> 1;

    const int m0 = blockIdx.y * 64;
    const int n0 = blockIdx.x * BN;
    const int e  = blockIdx.z;

    const int Mrows = g_cnt[e];
    if (m0 >= Mrows) return;
    const __half* B = h_wgu + (size_t)e * HID * (2 * IMOE);

    const int ar = tid >> 2, ac = (tid & 3) * 8;
    const __half* aP0;
    {
        int r0 = m0 + ar;
        int i0 = (r0 < Mrows) ? g_tok[e * N_TOK + r0] : 0;
        aP0 = h_x + (size_t)i0 * HID;
    }
    const int bk = tid >> 4, bc = (tid & 15) * 8;
    const __half* bPg = B + n0;
    const __half* bPu = B + Iact + n0;

    const uint32_t sbase = (uint32_t)__cvta_generic_to_shared(smem);
    const uint32_t dA0 = sbase + (uint32_t)(ar * A_PITCH + ac) * 2u;
    const uint32_t dG0 = sbase + (uint32_t)A64_BYTES + (uint32_t)(bk * B_PITCH + bc) * 2u;
    const uint32_t dG1 = dG0 + 16u * B_PITCH * 2u;
    const uint32_t dU0 = dG0 + (uint32_t)B_BYTES;
    const uint32_t dU1 = dG1 + (uint32_t)B_BYTES;

    const int ktiles = K / BK;

    float accg[2][4][4], accu[2][4][4];
    #pragma unroll
    for (int i = 0; i < 2; i++)
        #pragma unroll
        for (int j = 0; j < 4; j++)
            #pragma unroll
            for (int q = 0; q < 4; q++) { accg[i][j][q] = 0.f; accu[i][j][q] = 0.f; }

    #pragma unroll
    for (int s = 0; s < FSTAGES - 1; s++) {
        const int k0 = s * BK;
        const uint32_t so = (uint32_t)(s * F64STG_B);
        cp16(dA0 + so, aP0 + k0 + ac);
        cp16(dG0 + so, bPg + (size_t)(k0 + bk) * Nb + bc);
        cp16(dG1 + so, bPg + (size_t)(k0 + bk + 16) * Nb + bc);
        cp16(dU0 + so, bPu + (size_t)(k0 + bk) * Nb + bc);
        cp16(dU1 + so, bPu + (size_t)(k0 + bk + 16) * Nb + bc);
        cp_commit();
    }

    const int frow_l = (lane & 7) + ((lane >> 3) & 1) * 8;
    const int fhi_l  = (lane >> 4) & 1;
    const uint32_t aFrag = sbase + (uint32_t)(((wm * 32 + frow_l) * A_PITCH) + fhi_l * 8) * 2u;
    const uint32_t gFrag = sbase + (uint32_t)A64_BYTES
                         + (uint32_t)((frow_l * B_PITCH) + wn * 32 + fhi_l * 8) * 2u;

    for (int kt = 0; kt < ktiles; kt++) {
        cp_wait<FSTAGES - 2>();
        __syncthreads();

        const int kn = kt + FSTAGES - 1;
        if (kn < ktiles) {
            const int k0 = kn * BK;
            const uint32_t so = (uint32_t)((kn % FSTAGES) * F64STG_B);
            cp16(dA0 + so, aP0 + k0 + ac);
            cp16(dG0 + so, bPg + (size_t)(k0 + bk) * Nb + bc);
            cp16(dG1 + so, bPg + (size_t)(k0 + bk + 16) * Nb + bc);
            cp16(dU0 + so, bPu + (size_t)(k0 + bk) * Nb + bc);
            cp16(dU1 + so, bPu + (size_t)(k0 + bk + 16) * Nb + bc);
        }
        cp_commit();

        const uint32_t so = (uint32_t)((kt % FSTAGES) * F64STG_B);
        #pragma unroll
        for (int ks = 0; ks < 2; ks++) {
            const int kk = ks * 16;
            unsigned af[2][4], bg[4][2], bu[4][2];
            #pragma unroll
            for (int i = 0; i < 2; i++)
                ldsm_x4(af[i], aFrag + so + (uint32_t)(i * 16 * A_PITCH + kk) * 2u);
            #pragma unroll
            for (int p = 0; p < 2; p++) {
                unsigned t[4];
                ldsm_x4_t(t, gFrag + so + (uint32_t)(kk * B_PITCH + p * 16) * 2u);
                bg[2 * p][0] = t[0]; bg[2 * p][1] = t[1];
                bg[2 * p + 1][0] = t[2]; bg[2 * p + 1][1] = t[3];
                ldsm_x4_t(t, gFrag + so + (uint32_t)B_BYTES + (uint32_t)(kk * B_PITCH + p * 16) * 2u);
                bu[2 * p][0] = t[0]; bu[2 * p][1] = t[1];
                bu[2 * p + 1][0] = t[2]; bu[2 * p + 1][1] = t[3];
            }
            #pragma unroll
            for (int i = 0; i < 2; i++)
                #pragma unroll
                for (int j = 0; j < 4; j++) {
                    mma_f16(accg[i][j], af[i], bg[j]);
                    mma_f16(accu[i][j], af[i], bu[j]);
                }
        }
    }

    const int g = lane >> 2, tg = lane & 3;
    #pragma unroll
    for (int i = 0; i < 2; i++) {
        #pragma unroll
        for (int half = 0; half < 2; half++) {
            int gr = m0 + wm * 32 + i * 16 + g + half * 8;
            if (gr >= Mrows) continue;
            float w = g_wt[e * N_TOK + gr];
            __half* arow = h_act_e + ((size_t)e * N_TOK + gr) * Iact;
            #pragma unroll
            for (int j = 0; j < 4; j++) {
                int cc = n0 + wn * 32 + j * 8 + 2 * tg;
                float v0 = w * siluf(accg[i][j][half * 2 + 0]) * accu[i][j][half * 2 + 0];
                float v1 = w * siluf(accg[i][j][half * 2 + 1]) * accu[i][j][half * 2 + 1];
                __half2 hv = __floats2half2_rn(v0, v1);
                *(__half2*)(arow + cc) = hv;
            }
        }
    }
}

// ---------------- shared down-proj (BM=128, k-sliced; q0 store, q1-3 atomic add) ----------------
#define STAGES 4
#define STG_B (A_BYTES + B_BYTES)      // 18944
#define D64STG_B (A64_BYTES + B_BYTES) // 13824

__global__ void __launch_bounds__(256)
gemm_dn1(float* __restrict__ Cg, int Kstride, int N, int kbeg, int klen, int accum) {
    extern __shared__ __half smem[];

    const int tid  = threadIdx.x;
    const int lane = tid & 31, warp = tid >> 5;
    const int wm = warp & 1, wn = warp >> 1;

    const int m0 = blockIdx.y * BM;
    const int n0 = blockIdx.x * BN;

    const __half* A = h_act_s;
    const __half* B = h_swd;

    const int ar = tid >> 2, ac = (tid & 3) * 8;
    const __half* aP0 = A + (size_t)(m0 + ar) * Kstride + kbeg;
    const __half* aP1 = A + (size_t)(m0 + ar + 64) * Kstride + kbeg;
    const int bk = tid >> 4, bc = (tid & 15) * 8;
    const __half* bP = B + (size_t)kbeg * N + n0;

    const uint32_t sbase = (uint32_t)__cvta_generic_to_shared(smem);
    const uint32_t dA0 = sbase + (uint32_t)(ar * A_PITCH + ac) * 2u;
    const uint32_t dA1 = dA0 + 64u * A_PITCH * 2u;
    const uint32_t dB0 = sbase + (uint32_t)A_BYTES + (uint32_t)(bk * B_PITCH + bc) * 2u;
    const uint32_t dB1 = dB0 + 16u * B_PITCH * 2u;

    const int ktiles = klen / BK;

    float acc[4][4][4];
    #pragma unroll
    for (int i = 0; i < 4; i++)
        #pragma unroll
        for (int j = 0; j < 4; j++)
            #pragma unroll
            for (int q = 0; q < 4; q++) acc[i][j][q] = 0.f;

    #pragma unroll
    for (int s = 0; s < STAGES - 1; s++) {
        const int k0 = s * BK;
        const uint32_t so = (uint32_t)(s * STG_B);
        cp16(dA0 + so, aP0 + k0 + ac);
        cp16(dA1 + so, aP1 + k0 + ac);
        cp16(dB0 + so, bP + (size_t)(k0 + bk) * N + bc);
        cp16(dB1 + so, bP + (size_t)(k0 + bk + 16) * N + bc);
        cp_commit();
    }

    const int frow_l = (lane & 7) + ((lane >> 3) & 1) * 8;
    const int fhi_l  = (lane >> 4) & 1;
    const uint32_t aFrag = sbase + (uint32_t)(((wm * 64 + frow_l) * A_PITCH) + fhi_l * 8) * 2u;
    const uint32_t bFrag = sbase + (uint32_t)A_BYTES
                         + (uint32_t)((frow_l * B_PITCH) + wn * 32 + fhi_l * 8) * 2u;

    for (int kt = 0; kt < ktiles; kt++) {
        cp_wait<STAGES - 2>();
        __syncthreads();

        const int kn = kt + STAGES - 1;
        if (kn < ktiles) {
            const int k0 = kn * BK;
            const uint32_t so = (uint32_t)((kn & (STAGES - 1)) * STG_B);
            cp16(dA0 + so, aP0 + k0 + ac);
            cp16(dA1 + so, aP1 + k0 + ac);
            cp16(dB0 + so, bP + (size_t)(k0 + bk) * N + bc);
            cp16(dB1 + so, bP + (size_t)(k0 + bk + 16) * N + bc);
        }
        cp_commit();

        const uint32_t so = (uint32_t)((kt & (STAGES - 1)) * STG_B);
        #pragma unroll
        for (int ks = 0; ks < 2; ks++) {
            const int kk = ks * 16;
            unsigned af[4][4], bf[4][2];
            #pragma unroll
            for (int i = 0; i < 4; i++)
                ldsm_x4(af[i], aFrag + so + (uint32_t)(i * 16 * A_PITCH + kk) * 2u);
            #pragma unroll
            for (int p = 0; p < 2; p++) {
                unsigned t[4];
                ldsm_x4_t(t, bFrag + so + (uint32_t)(kk * B_PITCH + p * 16) * 2u);
                bf[2 * p][0] = t[0]; bf[2 * p][1] = t[1];
                bf[2 * p + 1][0] = t[2]; bf[2 * p + 1][1] = t[3];
            }
            #pragma unroll
            for (int i = 0; i < 4; i++)
                #pragma unroll
                for (int j = 0; j < 4; j++)
                    mma_f16(acc[i][j], af[i], bf[j]);
        }
    }

    const int g = lane >> 2, tg = lane & 3;
    #pragma unroll
    for (int i = 0; i < 4; i++) {
        #pragma unroll
        for (int half = 0; half < 2; half++) {
            int gr = m0 + wm * 64 + i * 16 + g + half * 8;
            float* crow = Cg + (size_t)gr * (size_t)N;
            float scale = g_sg[gr];
            #pragma unroll
            for (int j = 0; j < 4; j++) {
                int cc = n0 + wn * 32 + j * 8 + 2 * tg;
                float v0 = acc[i][j][half * 2 + 0] * scale;
                float v1 = acc[i][j][half * 2 + 1] * scale;
                if (accum) {
                    atomicAdd(crow + cc,     v0);
                    atomicAdd(crow + cc + 1, v1);
                } else {
                    *(float2*)(crow + cc) = make_float2(v0, v1);
                }
            }
        }
    }
}

// ---------------- expert down-proj, BM=64, atomic-add into out ----------------
__global__ void __launch_bounds__(256)
gemm_dn64(float* __restrict__ Cg, int Kstride, int N) {
    extern __shared__ __half smem[];

    const int tid  = threadIdx.x;
    const int lane = tid & 31, warp = tid >> 5;
    const int wm = warp & 1, wn = warp >> 1;

    const int m0 = blockIdx.y * 64;
    const int n0 = blockIdx.x * BN;
    const int e  = blockIdx.z;

    const int Mrows = g_cnt[e];
    if (m0 >= Mrows) return;
    const __half* A = h_act_e + (size_t)e * N_TOK * IMOE;
    const __half* B = h_wd + (size_t)e * IMOE * HID;

    const int ar = tid >> 2, ac = (tid & 3) * 8;
    const __half* aP0;
    {
        int r0 = m0 + ar;
        if (r0 >= Mrows) r0 = m0;
        aP0 = A + (size_t)r0 * Kstride;
    }
    const int bk = tid >> 4, bc = (tid & 15) * 8;
    const __half* bP = B + n0;

    const uint32_t sbase = (uint32_t)__cvta_generic_to_shared(smem);
    const uint32_t dA0 = sbase + (uint32_t)(ar * A_PITCH + ac) * 2u;
    const uint32_t dB0 = sbase + (uint32_t)A64_BYTES + (uint32_t)(bk * B_PITCH + bc) * 2u;
    const uint32_t dB1 = dB0 + 16u * B_PITCH * 2u;

    const int ktiles = Kstride / BK;

    float acc[2][4][4];
    #pragma unroll
    for (int i = 0; i < 2; i++)
        #pragma unroll
        for (int j = 0; j < 4; j++)
            #pragma unroll
            for (int q = 0; q < 4; q++) acc[i][j][q] = 0.f;

    #pragma unroll
    for (int s = 0; s < STAGES - 1; s++) {
        const int k0 = s * BK;
        const uint32_t so = (uint32_t)(s * D64STG_B);
        cp16(dA0 + so, aP0 + k0 + ac);
        cp16(dB0 + so, bP + (size_t)(k0 + bk) * N + bc);
        cp16(dB1 + so, bP + (size_t)(k0 + bk + 16) * N + bc);
        cp_commit();
    }

    const int frow_l = (lane & 7) + ((lane >> 3) & 1) * 8;
    const int fhi_l  = (lane >> 4) & 1;
    const uint32_t aFrag = sbase + (uint32_t)(((wm * 32 + frow_l) * A_PITCH) + fhi_l * 8) * 2u;
    const uint32_t bFrag = sbase + (uint32_t)A64_BYTES
                         + (uint32_t)((frow_l * B_PITCH) + wn * 32 + fhi_l * 8) * 2u;

    for (int kt = 0; kt < ktiles; kt++) {
        cp_wait<STAGES - 2>();
        __syncthreads();

        const int kn = kt + STAGES - 1;
        if (kn < ktiles) {
            const int k0 = kn * BK;
            const uint32_t so = (uint32_t)((kn & (STAGES - 1)) * D64STG_B);
            cp16(dA0 + so, aP0 + k0 + ac);
            cp16(dB0 + so, bP + (size_t)(k0 + bk) * N + bc);
            cp16(dB1 + so, bP + (size_t)(k0 + bk + 16) * N + bc);
        }
        cp_commit();

        const uint32_t so = (uint32_t)((kt & (STAGES - 1)) * D64STG_B);
        #pragma unroll
        for (int ks = 0; ks < 2; ks++) {
            const int kk = ks * 16;
            unsigned af[2][4], bf[4][2];
            #pragma unroll
            for (int i = 0; i < 2; i++)
                ldsm_x4(af[i], aFrag + so + (uint32_t)(i * 16 * A_PITCH + kk) * 2u);
            #pragma unroll
            for (int p = 0; p < 2; p++) {
                unsigned t[4];
                ldsm_x4_t(t, bFrag + so + (uint32_t)(kk * B_PITCH + p * 16) * 2u);
                bf[2 * p][0] = t[0]; bf[2 * p][1] = t[1];
                bf[2 * p + 1][0] = t[2]; bf[2 * p + 1][1] = t[3];
            }
            #pragma unroll
            for (int i = 0; i < 2; i++)
                #pragma unroll
                for (int j = 0; j < 4; j++)
                    mma_f16(acc[i][j], af[i], bf[j]);
        }
    }

    const int g = lane >> 2, tg = lane & 3;
    #pragma unroll
    for (int i = 0; i < 2; i++) {
        #pragma unroll
        for (int half = 0; half < 2; half++) {
            int gr = m0 + wm * 32 + i * 16 + g + half * 8;
            if (gr >= Mrows) continue;
            int t_ = g_tok[e * N_TOK + gr];
            float* crow = Cg + (size_t)t_ * (size_t)N;
            #pragma unroll
            for (int j = 0; j < 4; j++) {
                int cc = n0 + wn * 32 + j * 8 + 2 * tg;
                atomicAdd(crow + cc,     acc[i][j][half * 2 + 0]);
                atomicAdd(crow + cc + 1, acc[i][j][half * 2 + 1]);
            }
        }
    }
}

// ---------------- launch: round-14 schedule; dn kernels fused onto `out` ----------------
extern "C" void kernel_launch(void* const* d_in, const int* in_sizes, int n_in,
                              void* d_out, int out_size) {
    const float* x    = (const float*)d_in[0];
    const float* gw   = (const float*)d_in[1];
    const float* wgu  = (const float*)d_in[2];
    const float* wd   = (const float*)d_in[3];
    const float* swgu = (const float*)d_in[4];
    const float* swd  = (const float*)d_in[5];
    const float* sgw  = (const float*)d_in[6];
    float* out = (float*)d_out;

    static cudaStream_t s1 = nullptr, s2 = nullptr, s3 = nullptr;
    static cudaEvent_t ev_fork, ev_rt, ev_st[4], ev_swd, ev_wd,
                       ev_g0[4], ev_dn1q0, ev_dn1, ev_exp;
    if (s1 == nullptr) {
        cudaStreamCreateWithFlags(&s1, cudaStreamNonBlocking);
        cudaStreamCreateWithFlags(&s2, cudaStreamNonBlocking);
        cudaStreamCreateWithFlags(&s3, cudaStreamNonBlocking);
        cudaEventCreateWithFlags(&ev_fork, cudaEventDisableTiming);
        cudaEventCreateWithFlags(&ev_rt,   cudaEventDisableTiming);
        for (int q = 0; q < 4; q++) {
            cudaEventCreateWithFlags(&ev_st[q], cudaEventDisableTiming);
            cudaEventCreateWithFlags(&ev_g0[q], cudaEventDisableTiming);
        }
        cudaEventCreateWithFlags(&ev_swd,   cudaEventDisableTiming);
        cudaEventCreateWithFlags(&ev_wd,    cudaEventDisableTiming);
        cudaEventCreateWithFlags(&ev_dn1q0, cudaEventDisableTiming);
        cudaEventCreateWithFlags(&ev_dn1,   cudaEventDisableTiming);
        cudaEventCreateWithFlags(&ev_exp,   cudaEventDisableTiming);
    }

    const int fsmem   = FSTAGES * FSTG_B;    // 82944
    const int f64smem = FSTAGES * F64STG_B;  // 67584
    const int dsmem   = STAGES * STG_B;      // 75776
    const int d64smem = STAGES * D64STG_B;   // 55296
    cudaFuncSetAttribute(gemm_gu0,  cudaFuncAttributeMaxDynamicSharedMemorySize, fsmem);
    cudaFuncSetAttribute(gemm_gu64, cudaFuncAttributeMaxDynamicSharedMemorySize, f64smem);
    cudaFuncSetAttribute(gemm_dn1,  cudaFuncAttributeMaxDynamicSharedMemorySize, dsmem);
    cudaFuncSetAttribute(gemm_dn64, cudaFuncAttributeMaxDynamicSharedMemorySize, d64smem);

    // ---- fork ----
    init_kernel<<<1, 32>>>();
    cudaEventRecord(ev_fork, 0);
    cudaStreamWaitEvent(s1, ev_fork, 0);
    cudaStreamWaitEvent(s2, ev_fork, 0);
    cudaStreamWaitEvent(s3, ev_fork, 0);

    // s1: swgu strips first (unblock gu0 quarters asap), then swd, wd
    {
        const int sg = (HID * (QI / 8) * 2 + 255) / 256;
        for (int q = 0; q < 4; q++) {
            f2h_swgu_strip<<<sg, 256, 0, s1>>>(swgu, q * QI);
            cudaEventRecord(ev_st[q], s1);
        }
        int n8 = (ISH * HID) / 8;
        f2h_kernel<2><<<(n8 + 255) / 256, 256, 0, s1>>>((const float4*)swd, n8);
        cudaEventRecord(ev_swd, s1);
        n8 = (NEXP * IMOE * HID) / 8;
        f2h_kernel<4><<<(n8 + 255) / 256, 256, 0, s1>>>((const float4*)wd, n8);
        cudaEventRecord(ev_wd, s1);
    }

    // stream 0: router, then gu0 n-quarters gated on strip converts
    router_kernel<<<N_TOK, 256>>>(x, gw, sgw);
    cudaEventRecord(ev_rt, 0);
    for (int q = 0; q < 4; q++) {
        cudaStreamWaitEvent(0, ev_st[q], 0);
        gemm_gu0<<<dim3(QI / BN, N_TOK / BM, 1), 256, fsmem>>>(HID, 2 * ISH, ISH, q * QI);
        cudaEventRecord(ev_g0[q], 0);
    }

    // s3: dn1 k-chunks, chained quarter-by-quarter against gu0
    cudaStreamWaitEvent(s3, ev_swd, 0);
    for (int q = 0; q < 4; q++) {
        cudaStreamWaitEvent(s3, ev_g0[q], 0);
        gemm_dn1<<<dim3(HID / BN, N_TOK / BM, 1), 256, dsmem, s3>>>(
            out, ISH, HID, q * QI, QI, q > 0 ? 1 : 0);
        if (q == 0) cudaEventRecord(ev_dn1q0, s3);
    }
    cudaEventRecord(ev_dn1, s3);

    // s2: wgu convert, then expert chain (dn64 adds directly into out)
    {
        int n8 = (NEXP * HID * 2 * IMOE) / 8;
        f2h_kernel<3><<<(n8 + 255) / 256, 256, 0, s2>>>((const float4*)wgu, n8);
    }
    cudaStreamWaitEvent(s2, ev_rt, 0);
    gemm_gu64<<<dim3(IMOE / BN, N_TOK / 64, NEXP), 256, f64smem, s2>>>(HID, 2 * IMOE, IMOE);
    cudaStreamWaitEvent(s2, ev_wd, 0);
    cudaStreamWaitEvent(s2, ev_dn1q0, 0);   // out must hold dn1.q0's plain write first
    gemm_dn64<<<dim3(HID / BN, N_TOK / 64, NEXP), 256, d64smem, s2>>>(out, IMOE, HID);
    cudaEventRecord(ev_exp, s2);

    // join: stream 0 waits for both chains (no combine kernel needed)
    cudaStreamWaitEvent(0, ev_dn1, 0);
    cudaStreamWaitEvent(0, ev_exp, 0);
}